// round 16
// baseline (speedup 1.0000x reference)
#include <cuda_runtime.h>
#include <cuda_fp16.h>
#include <mma.h>
#include <cstdint>

using namespace nvcuda;

constexpr int NWIN = 8, CH = 1024, C2 = 512;
constexpr int SLAB = 256, WINSLABS = 6, GUARD = 256;
constexpr int ROWS_ALLOC = NWIN * WINSLABS * SLAB + 2 * GUARD;  // 12800
constexpr int KDIM = 27 * CH;                                    // 27648
constexpr int BM = 128, BN = 128, BK = 64;
constexpr int KCHUNKS = KDIM / BK;                               // 432

// conv1: 7 zero-partial slabs skipped -> 4900 valid rows
constexpr int VROWS1 = 4900;
constexpr int NMT1 = 39;
constexpr int SPLITS1 = 16;
constexpr int KCH1 = KCHUNKS / SPLITS1;   // 27
// conv2: all 6272 rows
constexpr int VROWS2 = 6272;
constexpr int NMT2 = 49;
constexpr int SPLITS2 = 3;
constexpr int KCH2 = KCHUNKS / SPLITS2;   // 144

// ldmatrix conflict-free strides: (stride/16) odd
constexpr int LDA = 72;    // elems -> 144 B rows
constexpr int LDB = 136;   // elems -> 272 B rows
constexpr int LDSTG = 132; // fp32 staging stride

// 3-stage ring: per stage A(128x64), B(64x128) fp16
constexpr int A_BUF = BM * LDA * 2;   // 18432 B
constexpr int B_BUF = BK * LDB * 2;   // 17408 B
constexpr int ST_A = 0;
constexpr int ST_B = A_BUF;
constexpr int STAGE_B = A_BUF + B_BUF;   // 35840
constexpr int SMEM_BYTES = 3 * STAGE_B;  // 107520 (2 CTAs/SM)

__device__ __half g_X1[(size_t)ROWS_ALLOC * CH];
__device__ __half g_X2[(size_t)ROWS_ALLOC * CH];
__device__ __half g_W1T[(size_t)KDIM * CH];   // [kidx*CH+ic][oc]
__device__ __half g_W2T[(size_t)KDIM * C2];
__device__ float g_part[(size_t)SPLITS1 * NMT1 * 8 * BM * BN];
__device__ float g_pooled[NWIN * C2];
__device__ float g_m1[NWIN * 512];
__device__ float g_m2[NWIN * 512];

// conv2 valid-row index (all 32 slabs) -> padded row
__device__ __forceinline__ int padded_row2(int i) {
    int t = i / 784, rem = i - t * 784;
    int d = rem / 196, s = rem - d * 196;
    int h = s / 14, w = s - h * 14;
    return (t * WINSLABS + d + 1) * SLAB + (h + 1) * 16 + (w + 1);
}

// conv1 compacted-row index (25 nonzero slabs) -> padded row; dummy rows -> 273 (safe)
__device__ __forceinline__ int padded_row1(int i) {
    if (i >= VROWS1) return 273;
    int s = i / 196, pos = i - s * 196;
    int t, d;
    if (s < 2)      { t = 1; d = s + 2; }
    else if (s < 5) { t = 2; d = s - 1; }
    else            { int q = s - 5; t = 3 + (q >> 2); d = q & 3; }
    int h = pos / 14, w = pos - h * 14;
    return (t * WINSLABS + d + 1) * SLAB + (h + 1) * 16 + (w + 1);
}

__device__ __forceinline__ uint32_t smem_u32(const void* p) {
    uint32_t a;
    asm("{ .reg .u64 t; cvta.to.shared.u64 t, %1; cvt.u32.u64 %0, t; }" : "=r"(a) : "l"(p));
    return a;
}
#define CP_ASYNC16(dst, src) \
    asm volatile("cp.async.cg.shared.global [%0], [%1], 16;" :: "r"(dst), "l"(src))
#define CP_COMMIT() asm volatile("cp.async.commit_group;" ::: "memory")
#define CP_WAIT0()  asm volatile("cp.async.wait_group 0;" ::: "memory")
#define CP_WAIT1()  asm volatile("cp.async.wait_group 1;" ::: "memory")

// ---------------- prep kernels ----------------
__global__ void k_zero_pooled() {
    int i = blockIdx.x * 256 + threadIdx.x;
    if (i < NWIN * C2) g_pooled[i] = 0.f;
}

__global__ void k_gather(const float* __restrict__ videos) {
    int i = blockIdx.x * 256 + threadIdx.x;
    constexpr int TOT = NWIN * 4 * 14 * 14 * CH;
    if (i >= TOT) return;
    int c = i & (CH - 1);
    int rest = i >> 10;
    int w = rest % 14; rest /= 14;
    int h = rest % 14; rest /= 14;
    int d = rest & 3;
    int t = rest >> 2;
    int frame = t - 4 + d;  // window t holds frames t-4..t-1 (zeros before 0)
    float v = (frame >= 0) ? videos[(size_t)(frame * CH + c) * 196 + h * 14 + w] : 0.f;
    size_t dst = (size_t)(GUARD + (t * WINSLABS + d + 1) * SLAB + (h + 1) * 16 + (w + 1)) * CH + c;
    g_X1[dst] = __float2half(v);
}

// fill the 7 all-zero-input conv1 output slabs with relu(b1)
__global__ void k_fill(const float* __restrict__ b1) {
    int i = blockIdx.x * 256 + threadIdx.x;
    constexpr int TOT = 7 * 196 * CH;
    if (i >= TOT) return;
    int c = i & (CH - 1);
    int rest = i >> 10;
    int s2 = rest / 196, pos = rest - s2 * 196;
    int t = (s2 < 4) ? 0 : (s2 < 6) ? 1 : 2;
    int d = (s2 < 4) ? s2 : (s2 < 6) ? s2 - 4 : 0;
    int h = pos / 14, w = pos - h * 14;
    size_t o = (size_t)(GUARD + (t * WINSLABS + d + 1) * SLAB + (h + 1) * 16 + (w + 1)) * CH + c;
    g_X2[o] = __float2half(fmaxf(b1[c], 0.f));
}

// conv weights (oc, ic, 27) -> WT[kidx*CH+ic][oc], fp16
template<int NOC>
__global__ void k_transpose(const float* __restrict__ w, __half* __restrict__ wt) {
    __shared__ float s[32][28];
    int ocBase = blockIdx.x * 32;
    int ic = blockIdx.y;
    for (int idx = threadIdx.x; idx < 32 * 27; idx += 256) {
        int oc = idx / 27, kk = idx - oc * 27;
        s[oc][kk] = w[((size_t)(ocBase + oc) * CH + ic) * 27 + kk];
    }
    __syncthreads();
    for (int idx = threadIdx.x; idx < 27 * 32; idx += 256) {
        int kk = idx >> 5, oc = idx & 31;
        wt[((size_t)kk * CH + ic) * NOC + ocBase + oc] = __float2half(s[oc][kk]);
    }
}

// ---- implicit-conv GEMM: fp16, BK=64, 3-stage cp.async, ptxas-scheduled frags ----
template<int N, bool L2, int SPL, int NMT, int KCH>
__global__ void __launch_bounds__(256, 2)
k_gemm(int dummy) {
    const __half* __restrict__ X = (L2 ? g_X2 : g_X1) + (size_t)GUARD * CH;
    const __half* __restrict__ W = L2 ? g_W2T : g_W1T;
    constexpr int NB = N / BN;

    extern __shared__ __align__(128) char smem_raw[];
    const uint32_t sbase = smem_u32(smem_raw);

    const int tid = threadIdx.x;
    const int mtile = blockIdx.x;
    const int nBase = blockIdx.y * BN;
    const int split = blockIdx.z;
    const int k0 = split * KCH;

    // per-thread A source rows (4 rows, fixed across K loop)
    const int r0 = tid >> 3;          // 0..31
    long pr[4];
#pragma unroll
    for (int it = 0; it < 4; it++) {
        int gi = mtile * BM + r0 + it * 32;
        pr[it] = L2 ? padded_row2(gi) : padded_row1(gi);
    }
    const int ac = (tid & 7) * 8;     // A column elem offset within 64

    wmma::fragment<wmma::accumulator, 16, 16, 16, float> acc[4][2];
#pragma unroll
    for (int i = 0; i < 4; i++)
#pragma unroll
        for (int j = 0; j < 2; j++) wmma::fill_fragment(acc[i][j], 0.f);

    const int warpId = tid >> 5;
    const int warpM = warpId >> 2;
    const int warpN = warpId & 3;

    auto loadChunk = [&](int kt, int stage) {
        const int kidx = kt >> 4;             // tap 0..26
        const int icBase = (kt & 15) << 6;    // 64-ch block
        const int kd = kidx / 9, r9 = kidx - kd * 9;
        const int kh = r9 / 3, kw = r9 - kh * 3;
        const long off = (long)(kd - 1) * SLAB + (kh - 1) * 16 + (kw - 1);
        const uint32_t sb = sbase + stage * STAGE_B;
#pragma unroll
        for (int it = 0; it < 4; it++) {
            const long so = (pr[it] + off) * CH + icBase + ac;
            CP_ASYNC16(sb + ST_A + (r0 + it * 32) * (LDA * 2) + ac * 2, X + so);
        }
        const size_t wb = (size_t)kt * BK * N + nBase;
#pragma unroll
        for (int it = 0; it < 4; it++) {
            int v = it * 256 + tid;
            int row = v >> 4, c = v & 15;     // 64 rows x 16 segs
            CP_ASYNC16(sb + ST_B + row * (LDB * 2) + c * 16, W + wb + (size_t)row * N + c * 8);
        }
    };

    loadChunk(k0, 0);     CP_COMMIT();
    loadChunk(k0 + 1, 1); CP_COMMIT();

    int stage = 0, nstage = 2;
    for (int kk = 0; kk < KCH; kk++) {
        if (kk < KCH - 1) CP_WAIT1(); else CP_WAIT0();
        __syncthreads();
        if (kk + 2 < KCH) {
            loadChunk(k0 + kk + 2, nstage);
            CP_COMMIT();
        }
        const char* sb = smem_raw + stage * STAGE_B;
        const __half* aa = (const __half*)(sb + ST_A) + warpM * 64 * LDA;
        const __half* bb = (const __half*)(sb + ST_B) + warpN * 32;

        // single-buffered fragments; unrolled body lets ptxas pipeline within
        // the 128-reg budget (acc 64 + fa 32 + fb 16 + addr ~ 120, no spill)
#pragma unroll
        for (int ks = 0; ks < 4; ks++) {
            wmma::fragment<wmma::matrix_b, 16, 16, 16, __half, wmma::row_major> fb[2];
#pragma unroll
            for (int j = 0; j < 2; j++)
                wmma::load_matrix_sync(fb[j], bb + ks * 16 * LDB + j * 16, LDB);
            wmma::fragment<wmma::matrix_a, 16, 16, 16, __half, wmma::row_major> fa[4];
#pragma unroll
            for (int i = 0; i < 4; i++)
                wmma::load_matrix_sync(fa[i], aa + (i * 16) * LDA + ks * 16, LDA);
#pragma unroll
            for (int i = 0; i < 4; i++)
#pragma unroll
                for (int j = 0; j < 2; j++)
                    wmma::mma_sync(acc[i][j], fa[i], fb[j], acc[i][j]);
        }
        stage = (stage + 1 == 3) ? 0 : stage + 1;
        nstage = (nstage + 1 == 3) ? 0 : nstage + 1;
    }
    __syncthreads();

    // stage + coalesced fp32 partial store (67584 B <= 107520)
    float* Stage = (float*)smem_raw;
#pragma unroll
    for (int i = 0; i < 4; i++)
#pragma unroll
        for (int j = 0; j < 2; j++)
            wmma::store_matrix_sync(Stage + (warpM * 64 + i * 16) * LDSTG + warpN * 32 + j * 16,
                                    acc[i][j], LDSTG, wmma::mem_row_major);
    __syncthreads();

    float* dst = g_part + ((size_t)(split * NMT + mtile) * NB + blockIdx.y) * (BM * BN);
#pragma unroll
    for (int it = 0; it < 16; it++) {
        int v = it * 256 + tid;
        int row = v >> 5, c4 = (v & 31) * 4;
        *(float4*)(dst + row * BN + c4) = *(const float4*)(Stage + row * LDSTG + c4);
    }
}

// conv1 epilogue: sum SPLITS1 partials + bias + relu -> X2 fp16 (skip dummy rows)
__global__ void k_epi1(const float* __restrict__ bias) {
    const int mtile = blockIdx.x, nblk = blockIdx.y;
    const int col = threadIdx.x & 127, rh = threadIdx.x >> 7;
    const size_t tile_sz = (size_t)BM * BN;
    const size_t tb = ((size_t)mtile * 8 + nblk) * tile_sz;
    const float b = bias[nblk * 128 + col];
    for (int rr = rh * 64; rr < rh * 64 + 64; rr++) {
        int gi = mtile * BM + rr;
        if (gi >= VROWS1) break;
        int e = rr * BN + col;
        float v = 0.f;
#pragma unroll
        for (int s = 0; s < SPLITS1; s++)
            v += g_part[(size_t)s * NMT1 * 8 * tile_sz + tb + e];
        v = fmaxf(v + b, 0.f);
        size_t o = (size_t)(GUARD + padded_row1(gi)) * CH + nblk * 128 + col;
        g_X2[o] = __float2half(v);
    }
}

// conv2 epilogue: sum SPLITS2 partials + bias + relu + maxpool -> g_pooled
__global__ void k_epi2(const float* __restrict__ bias) {
    const int mtile = blockIdx.x, nblk = blockIdx.y;
    const int col = threadIdx.x;  // 128 threads
    const size_t tile_sz = (size_t)BM * BN;
    const size_t tb = ((size_t)mtile * 4 + nblk) * tile_sz;
    const float* P0 = g_part + tb;
    const float* P1 = g_part + (size_t)NMT2 * 4 * tile_sz + tb;
    const float* P2 = g_part + (size_t)2 * NMT2 * 4 * tile_sz + tb;
    const float b = bias[nblk * 128 + col];
    float m = 0.f;
    int curt = (mtile * BM) / 784;
    for (int rr = 0; rr < BM; rr++) {
        int t = (mtile * BM + rr) / 784;
        if (t != curt) {
            atomicMax((int*)&g_pooled[curt * C2 + nblk * 128 + col], __float_as_int(m));
            m = 0.f;
            curt = t;
        }
        int e = rr * BN + col;
        m = fmaxf(m, P0[e] + P1[e] + P2[e] + b);
    }
    atomicMax((int*)&g_pooled[curt * C2 + nblk * 128 + col], __float_as_int(m));
}

// ---------------- tiny MLP ----------------
template<int IN, int OUT>
__global__ void k_fc(const float* __restrict__ W, const float* __restrict__ b,
                     const float* __restrict__ x, float* __restrict__ y) {
    int w = threadIdx.x >> 5, lane = threadIdx.x & 31;
    int o = blockIdx.x * 8 + w, t = blockIdx.y;
    float s = 0.f;
    for (int i = lane; i < IN; i += 32) s += x[t * IN + i] * W[(size_t)o * IN + i];
#pragma unroll
    for (int d = 16; d; d >>= 1) s += __shfl_down_sync(0xffffffffu, s, d);
    if (lane == 0) y[t * OUT + o] = fmaxf(s + b[o], 0.f);
}

extern "C" void kernel_launch(void* const* d_in, const int* in_sizes, int n_in,
                              void* d_out, int out_size) {
    const float* videos  = (const float*)d_in[0];
    const float* conv1_w = (const float*)d_in[1];
    const float* conv1_b = (const float*)d_in[2];
    const float* conv2_w = (const float*)d_in[3];
    const float* conv2_b = (const float*)d_in[4];
    const float* l1_w = (const float*)d_in[5];
    const float* l1_b = (const float*)d_in[6];
    const float* l2_w = (const float*)d_in[7];
    const float* l2_b = (const float*)d_in[8];
    const float* l3_w = (const float*)d_in[9];
    const float* l3_b = (const float*)d_in[10];
    float* out = (float*)d_out;

    auto g1 = k_gemm<CH, false, SPLITS1, NMT1, KCH1>;
    auto g2 = k_gemm<C2, true,  SPLITS2, NMT2, KCH2>;
    cudaFuncSetAttribute(g1, cudaFuncAttributeMaxDynamicSharedMemorySize, SMEM_BYTES);
    cudaFuncSetAttribute(g2, cudaFuncAttributeMaxDynamicSharedMemorySize, SMEM_BYTES);

    __half *w1t, *w2t;
    float *pooled, *m1, *m2;
    cudaGetSymbolAddress((void**)&w1t, g_W1T);
    cudaGetSymbolAddress((void**)&w2t, g_W2T);
    cudaGetSymbolAddress((void**)&pooled, g_pooled);
    cudaGetSymbolAddress((void**)&m1, g_m1);
    cudaGetSymbolAddress((void**)&m2, g_m2);

    constexpr int TOT = NWIN * 4 * 14 * 14 * CH;
    // g1 in the ncu-profiled slot (4th launch)
    k_gather<<<(TOT + 255) / 256, 256>>>(videos);
    k_transpose<CH><<<dim3(CH / 32, CH), 256>>>(conv1_w, w1t);
    k_zero_pooled<<<(NWIN * C2 + 255) / 256, 256>>>();

    g1<<<dim3(NMT1, CH / BN, SPLITS1), 256, SMEM_BYTES>>>(0);

    k_transpose<C2><<<dim3(C2 / 32, CH), 256>>>(conv2_w, w2t);
    k_fill<<<(7 * 196 * CH + 255) / 256, 256>>>(conv1_b);
    k_epi1<<<dim3(NMT1, CH / BN), 256>>>(conv1_b);

    g2<<<dim3(NMT2, C2 / BN, SPLITS2), 256, SMEM_BYTES>>>(0);
    k_epi2<<<dim3(NMT2, C2 / BN), 128>>>(conv2_b);

    k_fc<512, 512><<<dim3(64, NWIN), 256>>>(l1_w, l1_b, pooled, m1);
    k_fc<512, 512><<<dim3(64, NWIN), 256>>>(l2_w, l2_b, m1, m2);
    k_fc<512, 128><<<dim3(16, NWIN), 256>>>(l3_w, l3_b, m2, out);
}

// round 17
// speedup vs baseline: 1.0282x; 1.0282x over previous
#include <cuda_runtime.h>
#include <cuda_fp16.h>
#include <mma.h>
#include <cstdint>

using namespace nvcuda;

constexpr int NWIN = 8, CH = 1024, C2 = 512;
constexpr int SLAB = 256, WINSLABS = 6, GUARD = 256;
constexpr int ROWS_ALLOC = NWIN * WINSLABS * SLAB + 2 * GUARD;  // 12800
constexpr int KDIM = 27 * CH;                                    // 27648
constexpr int BM = 128, BN = 128, BK = 64;
constexpr int KCHUNKS = KDIM / BK;                               // 432

// conv1: 7 zero-partial slabs skipped -> 4900 valid rows
constexpr int VROWS1 = 4900;
constexpr int NMT1 = 39;
constexpr int SPLITS1 = 16;
constexpr int KCH1 = KCHUNKS / SPLITS1;   // 27
// conv2: all 6272 rows
constexpr int VROWS2 = 6272;
constexpr int NMT2 = 49;
constexpr int SPLITS2 = 3;
constexpr int KCH2 = KCHUNKS / SPLITS2;   // 144

// ldmatrix conflict-free strides: (stride/16) odd
constexpr int LDA = 72;    // elems -> 144 B rows
constexpr int LDB = 136;   // elems -> 272 B rows
constexpr int LDSTG = 132; // fp32 staging stride

// 3-stage ring: per stage A(128x64), B(64x128) fp16
constexpr int A_BUF = BM * LDA * 2;   // 18432 B
constexpr int B_BUF = BK * LDB * 2;   // 17408 B
constexpr int ST_A = 0;
constexpr int ST_B = A_BUF;
constexpr int STAGE_B = A_BUF + B_BUF;   // 35840
constexpr int SMEM_BYTES = 3 * STAGE_B;  // 107520 (2 CTAs/SM)

// tap row-offsets: off(kidx) = (kd-1)*SLAB + (kh-1)*16 + (kw-1), kidx = kd*9+kh*3+kw
__device__ const int c_off[27] = {
    -273, -272, -271, -257, -256, -255, -241, -240, -239,
     -17,  -16,  -15,   -1,    0,    1,   15,   16,   17,
     239,  240,  241,  255,  256,  257,  271,  272,  273
};

__device__ __half g_X1[(size_t)ROWS_ALLOC * CH];
__device__ __half g_X2[(size_t)ROWS_ALLOC * CH];
__device__ __half g_W1T[(size_t)KDIM * CH];   // [kidx*CH+ic][oc]
__device__ __half g_W2T[(size_t)KDIM * C2];
__device__ float g_part[(size_t)SPLITS1 * NMT1 * 8 * BM * BN];
__device__ float g_pooled[NWIN * C2];
__device__ float g_m1[NWIN * 512];
__device__ float g_m2[NWIN * 512];

// conv2 valid-row index (all 32 slabs) -> padded row
__device__ __forceinline__ int padded_row2(int i) {
    int t = i / 784, rem = i - t * 784;
    int d = rem / 196, s = rem - d * 196;
    int h = s / 14, w = s - h * 14;
    return (t * WINSLABS + d + 1) * SLAB + (h + 1) * 16 + (w + 1);
}

// conv1 compacted-row index (25 nonzero slabs) -> padded row; dummy rows -> 273 (safe)
__device__ __forceinline__ int padded_row1(int i) {
    if (i >= VROWS1) return 273;
    int s = i / 196, pos = i - s * 196;
    int t, d;
    if (s < 2)      { t = 1; d = s + 2; }
    else if (s < 5) { t = 2; d = s - 1; }
    else            { int q = s - 5; t = 3 + (q >> 2); d = q & 3; }
    int h = pos / 14, w = pos - h * 14;
    return (t * WINSLABS + d + 1) * SLAB + (h + 1) * 16 + (w + 1);
}

__device__ __forceinline__ uint32_t smem_u32(const void* p) {
    uint32_t a;
    asm("{ .reg .u64 t; cvta.to.shared.u64 t, %1; cvt.u32.u64 %0, t; }" : "=r"(a) : "l"(p));
    return a;
}
#define CP_ASYNC16(dst, src) \
    asm volatile("cp.async.cg.shared.global [%0], [%1], 16;" :: "r"(dst), "l"(src))
#define CP_COMMIT() asm volatile("cp.async.commit_group;" ::: "memory")
#define CP_WAIT0()  asm volatile("cp.async.wait_group 0;" ::: "memory")
#define CP_WAIT1()  asm volatile("cp.async.wait_group 1;" ::: "memory")

// ---------------- prep kernels ----------------
__global__ void k_zero_pooled() {
    int i = blockIdx.x * 256 + threadIdx.x;
    if (i < NWIN * C2) g_pooled[i] = 0.f;
}

__global__ void k_gather(const float* __restrict__ videos) {
    int i = blockIdx.x * 256 + threadIdx.x;
    constexpr int TOT = NWIN * 4 * 14 * 14 * CH;
    if (i >= TOT) return;
    int c = i & (CH - 1);
    int rest = i >> 10;
    int w = rest % 14; rest /= 14;
    int h = rest % 14; rest /= 14;
    int d = rest & 3;
    int t = rest >> 2;
    int frame = t - 4 + d;  // window t holds frames t-4..t-1 (zeros before 0)
    float v = (frame >= 0) ? videos[(size_t)(frame * CH + c) * 196 + h * 14 + w] : 0.f;
    size_t dst = (size_t)(GUARD + (t * WINSLABS + d + 1) * SLAB + (h + 1) * 16 + (w + 1)) * CH + c;
    g_X1[dst] = __float2half(v);
}

// fill the 7 all-zero-input conv1 output slabs with relu(b1)
__global__ void k_fill(const float* __restrict__ b1) {
    int i = blockIdx.x * 256 + threadIdx.x;
    constexpr int TOT = 7 * 196 * CH;
    if (i >= TOT) return;
    int c = i & (CH - 1);
    int rest = i >> 10;
    int s2 = rest / 196, pos = rest - s2 * 196;
    int t = (s2 < 4) ? 0 : (s2 < 6) ? 1 : 2;
    int d = (s2 < 4) ? s2 : (s2 < 6) ? s2 - 4 : 0;
    int h = pos / 14, w = pos - h * 14;
    size_t o = (size_t)(GUARD + (t * WINSLABS + d + 1) * SLAB + (h + 1) * 16 + (w + 1)) * CH + c;
    g_X2[o] = __float2half(fmaxf(b1[c], 0.f));
}

// conv weights (oc, ic, 27) -> WT[kidx*CH+ic][oc]; 64-oc blocks for 128B writes
template<int NOC>
__global__ void k_transpose(const float* __restrict__ w, __half* __restrict__ wt) {
    __shared__ float s[64][28];
    int ocBase = blockIdx.x * 64;
    int ic = blockIdx.y;
    for (int idx = threadIdx.x; idx < 64 * 27; idx += 256) {
        int oc = idx / 27, kk = idx - oc * 27;
        s[oc][kk] = w[((size_t)(ocBase + oc) * CH + ic) * 27 + kk];
    }
    __syncthreads();
    for (int idx = threadIdx.x; idx < 27 * 64; idx += 256) {
        int kk = idx >> 6, oc = idx & 63;
        wt[((size_t)kk * CH + ic) * NOC + ocBase + oc] = __float2half(s[oc][kk]);
    }
}

// ---- implicit-conv GEMM: fp16, BK=64, 3-stage cp.async, frag double-buffer ----
template<int N, bool L2, int SPL, int NMT, int KCH>
__global__ void __launch_bounds__(256, 2)
k_gemm(int dummy) {
    const __half* __restrict__ X = (L2 ? g_X2 : g_X1) + (size_t)GUARD * CH;
    const __half* __restrict__ W = L2 ? g_W2T : g_W1T;
    constexpr int NB = N / BN;

    extern __shared__ __align__(128) char smem_raw[];
    const uint32_t sbase = smem_u32(smem_raw);

    const int tid = threadIdx.x;
    const int mtile = blockIdx.x;
    const int nBase = blockIdx.y * BN;
    const int split = blockIdx.z;
    const int k0 = split * KCH;

    // per-thread A source rows (4 rows, fixed across K loop)
    const int r0 = tid >> 3;          // 0..31
    long pr[4];
#pragma unroll
    for (int it = 0; it < 4; it++) {
        int gi = mtile * BM + r0 + it * 32;
        pr[it] = L2 ? padded_row2(gi) : padded_row1(gi);
    }
    const int ac = (tid & 7) * 8;     // A column elem offset within 64

    wmma::fragment<wmma::accumulator, 16, 16, 16, float> acc[4][2];
#pragma unroll
    for (int i = 0; i < 4; i++)
#pragma unroll
        for (int j = 0; j < 2; j++) wmma::fill_fragment(acc[i][j], 0.f);

    const int warpId = tid >> 5;
    const int warpM = warpId >> 2;
    const int warpN = warpId & 3;

    // cheap per-chunk addressing: table lookup for tap offset, incremental B base
    auto loadChunk = [&](int kt, int stage) {
        const int off = c_off[kt >> 4];       // tap row offset
        const int icBase = (kt & 15) << 6;    // 64-ch block
        const uint32_t sb = sbase + stage * STAGE_B;
#pragma unroll
        for (int it = 0; it < 4; it++) {
            const long so = (pr[it] + off) * CH + icBase + ac;
            CP_ASYNC16(sb + ST_A + (r0 + it * 32) * (LDA * 2) + ac * 2, X + so);
        }
        const __half* wsrc = W + (size_t)kt * BK * N + nBase;
#pragma unroll
        for (int it = 0; it < 4; it++) {
            int v = it * 256 + tid;
            int row = v >> 4, c = v & 15;     // 64 rows x 16 segs
            CP_ASYNC16(sb + ST_B + row * (LDB * 2) + c * 16, wsrc + (size_t)row * N + c * 8);
        }
    };

    loadChunk(k0, 0);     CP_COMMIT();
    loadChunk(k0 + 1, 1); CP_COMMIT();

    wmma::fragment<wmma::matrix_a, 16, 16, 16, __half, wmma::row_major> fa[2][4];
    wmma::fragment<wmma::matrix_b, 16, 16, 16, __half, wmma::row_major> fb[2][2];

    int stage = 0, nstage = 2;
    for (int kk = 0; kk < KCH; kk++) {
        if (kk < KCH - 1) CP_WAIT1(); else CP_WAIT0();
        __syncthreads();
        if (kk + 2 < KCH) {
            loadChunk(k0 + kk + 2, nstage);
            CP_COMMIT();
        }
        const char* sb = smem_raw + stage * STAGE_B;
        const __half* aa = (const __half*)(sb + ST_A) + warpM * 64 * LDA;
        const __half* bb = (const __half*)(sb + ST_B) + warpN * 32;

        // preload ks=0 fragments
#pragma unroll
        for (int j = 0; j < 2; j++)
            wmma::load_matrix_sync(fb[0][j], bb + j * 16, LDB);
#pragma unroll
        for (int i = 0; i < 4; i++)
            wmma::load_matrix_sync(fa[0][i], aa + (i * 16) * LDA, LDA);

#pragma unroll
        for (int ks = 0; ks < 4; ks++) {
            const int p = ks & 1;
            if (ks < 3) {   // prefetch ks+1 fragments into alternate set
#pragma unroll
                for (int j = 0; j < 2; j++)
                    wmma::load_matrix_sync(fb[p ^ 1][j],
                        bb + (ks + 1) * 16 * LDB + j * 16, LDB);
#pragma unroll
                for (int i = 0; i < 4; i++)
                    wmma::load_matrix_sync(fa[p ^ 1][i],
                        aa + (i * 16) * LDA + (ks + 1) * 16, LDA);
            }
#pragma unroll
            for (int i = 0; i < 4; i++)
#pragma unroll
                for (int j = 0; j < 2; j++)
                    wmma::mma_sync(acc[i][j], fa[p][i], fb[p][j], acc[i][j]);
        }
        stage = (stage + 1 == 3) ? 0 : stage + 1;
        nstage = (nstage + 1 == 3) ? 0 : nstage + 1;
    }
    __syncthreads();

    // stage + coalesced fp32 partial store (67584 B <= 107520)
    float* Stage = (float*)smem_raw;
#pragma unroll
    for (int i = 0; i < 4; i++)
#pragma unroll
        for (int j = 0; j < 2; j++)
            wmma::store_matrix_sync(Stage + (warpM * 64 + i * 16) * LDSTG + warpN * 32 + j * 16,
                                    acc[i][j], LDSTG, wmma::mem_row_major);
    __syncthreads();

    float* dst = g_part + ((size_t)(split * NMT + mtile) * NB + blockIdx.y) * (BM * BN);
#pragma unroll
    for (int it = 0; it < 16; it++) {
        int v = it * 256 + tid;
        int row = v >> 5, c4 = (v & 31) * 4;
        *(float4*)(dst + row * BN + c4) = *(const float4*)(Stage + row * LDSTG + c4);
    }
}

// conv1 epilogue: sum SPLITS1 partials + bias + relu -> X2 fp16 (skip dummy rows)
__global__ void k_epi1(const float* __restrict__ bias) {
    const int mtile = blockIdx.x, nblk = blockIdx.y;
    const int col = threadIdx.x & 127, rh = threadIdx.x >> 7;
    const size_t tile_sz = (size_t)BM * BN;
    const size_t tb = ((size_t)mtile * 8 + nblk) * tile_sz;
    const float b = bias[nblk * 128 + col];
    for (int rr = rh * 64; rr < rh * 64 + 64; rr++) {
        int gi = mtile * BM + rr;
        if (gi >= VROWS1) break;
        int e = rr * BN + col;
        float v = 0.f;
#pragma unroll
        for (int s = 0; s < SPLITS1; s++)
            v += g_part[(size_t)s * NMT1 * 8 * tile_sz + tb + e];
        v = fmaxf(v + b, 0.f);
        size_t o = (size_t)(GUARD + padded_row1(gi)) * CH + nblk * 128 + col;
        g_X2[o] = __float2half(v);
    }
}

// conv2 epilogue: sum SPLITS2 partials + bias + relu + maxpool -> g_pooled
__global__ void k_epi2(const float* __restrict__ bias) {
    const int mtile = blockIdx.x, nblk = blockIdx.y;
    const int col = threadIdx.x;  // 128 threads
    const size_t tile_sz = (size_t)BM * BN;
    const size_t tb = ((size_t)mtile * 4 + nblk) * tile_sz;
    const float* P0 = g_part + tb;
    const float* P1 = g_part + (size_t)NMT2 * 4 * tile_sz + tb;
    const float* P2 = g_part + (size_t)2 * NMT2 * 4 * tile_sz + tb;
    const float b = bias[nblk * 128 + col];
    float m = 0.f;
    int curt = (mtile * BM) / 784;
    for (int rr = 0; rr < BM; rr++) {
        int t = (mtile * BM + rr) / 784;
        if (t != curt) {
            atomicMax((int*)&g_pooled[curt * C2 + nblk * 128 + col], __float_as_int(m));
            m = 0.f;
            curt = t;
        }
        int e = rr * BN + col;
        m = fmaxf(m, P0[e] + P1[e] + P2[e] + b);
    }
    atomicMax((int*)&g_pooled[curt * C2 + nblk * 128 + col], __float_as_int(m));
}

// ---------------- tiny MLP ----------------
template<int IN, int OUT>
__global__ void k_fc(const float* __restrict__ W, const float* __restrict__ b,
                     const float* __restrict__ x, float* __restrict__ y) {
    int w = threadIdx.x >> 5, lane = threadIdx.x & 31;
    int o = blockIdx.x * 8 + w, t = blockIdx.y;
    float s = 0.f;
    for (int i = lane; i < IN; i += 32) s += x[t * IN + i] * W[(size_t)o * IN + i];
#pragma unroll
    for (int d = 16; d; d >>= 1) s += __shfl_down_sync(0xffffffffu, s, d);
    if (lane == 0) y[t * OUT + o] = fmaxf(s + b[o], 0.f);
}

extern "C" void kernel_launch(void* const* d_in, const int* in_sizes, int n_in,
                              void* d_out, int out_size) {
    const float* videos  = (const float*)d_in[0];
    const float* conv1_w = (const float*)d_in[1];
    const float* conv1_b = (const float*)d_in[2];
    const float* conv2_w = (const float*)d_in[3];
    const float* conv2_b = (const float*)d_in[4];
    const float* l1_w = (const float*)d_in[5];
    const float* l1_b = (const float*)d_in[6];
    const float* l2_w = (const float*)d_in[7];
    const float* l2_b = (const float*)d_in[8];
    const float* l3_w = (const float*)d_in[9];
    const float* l3_b = (const float*)d_in[10];
    float* out = (float*)d_out;

    auto g1 = k_gemm<CH, false, SPLITS1, NMT1, KCH1>;
    auto g2 = k_gemm<C2, true,  SPLITS2, NMT2, KCH2>;
    cudaFuncSetAttribute(g1, cudaFuncAttributeMaxDynamicSharedMemorySize, SMEM_BYTES);
    cudaFuncSetAttribute(g2, cudaFuncAttributeMaxDynamicSharedMemorySize, SMEM_BYTES);

    __half *w1t, *w2t;
    float *pooled, *m1, *m2;
    cudaGetSymbolAddress((void**)&w1t, g_W1T);
    cudaGetSymbolAddress((void**)&w2t, g_W2T);
    cudaGetSymbolAddress((void**)&pooled, g_pooled);
    cudaGetSymbolAddress((void**)&m1, g_m1);
    cudaGetSymbolAddress((void**)&m2, g_m2);

    constexpr int TOT = NWIN * 4 * 14 * 14 * CH;
    // g1 in the ncu-profiled slot (4th launch)
    k_gather<<<(TOT + 255) / 256, 256>>>(videos);
    k_transpose<CH><<<dim3(CH / 64, CH), 256>>>(conv1_w, w1t);
    k_zero_pooled<<<(NWIN * C2 + 255) / 256, 256>>>();

    g1<<<dim3(NMT1, CH / BN, SPLITS1), 256, SMEM_BYTES>>>(0);

    k_transpose<C2><<<dim3(C2 / 64, CH), 256>>>(conv2_w, w2t);
    k_fill<<<(7 * 196 * CH + 255) / 256, 256>>>(conv1_b);
    k_epi1<<<dim3(NMT1, CH / BN), 256>>>(conv1_b);

    g2<<<dim3(NMT2, C2 / BN, SPLITS2), 256, SMEM_BYTES>>>(0);
    k_epi2<<<dim3(NMT2, C2 / BN), 128>>>(conv2_b);

    k_fc<512, 512><<<dim3(64, NWIN), 256>>>(l1_w, l1_b, pooled, m1);
    k_fc<512, 512><<<dim3(64, NWIN), 256>>>(l2_w, l2_b, m1, m2);
    k_fc<512, 128><<<dim3(16, NWIN), 256>>>(l3_w, l3_b, m2, out);
}